// round 4
// baseline (speedup 1.0000x reference)
#include <cuda_runtime.h>
#include <math.h>

#define DIM      128
#define DIM4     32          // DIM / 4
#define MAXN     100000
#define MAXE     1600000
#define BETA     0.001f
#define ONE_MB   0.999f      // 1 - BETA
#define EPS_NORM 1e-12f

// ---------------- device scratch (no allocations allowed) ----------------
__device__ float g_support[(size_t)MAXN * DIM];   // 51.2 MB, L2-resident
__device__ int   g_count [MAXN];
__device__ int   g_rowptr[MAXN + 1];
__device__ int   g_head  [MAXN];
__device__ int   g_col   [MAXE];
__device__ float g_val   [MAXE];

// ---------------- 0. zero the per-row edge counters ----------------------
__global__ void zero_count_kernel(int n) {
    int i = blockIdx.x * blockDim.x + threadIdx.x;
    if (i < n) g_count[i] = 0;
}

// ---------------- 1. support = input @ W  (fp32 SIMT GEMM) ---------------
// BM=128 rows per CTA, full N=128 cols, BK=32, 256 threads, 8x8 microtile.
__global__ __launch_bounds__(256) void gemm_kernel(
    const float* __restrict__ A,   // [M, 128]
    const float* __restrict__ W,   // [128, 128]
    int M)
{
    __shared__ float As[32 * 128];   // As[k][m]
    __shared__ float Bs[32 * 128];   // Bs[k][n]

    const int tid = threadIdx.x;
    const int tx  = tid & 15;
    const int ty  = tid >> 4;
    const int m0  = blockIdx.x * 128;

    float acc[8][8];
#pragma unroll
    for (int i = 0; i < 8; i++)
#pragma unroll
        for (int j = 0; j < 8; j++) acc[i][j] = 0.f;

    const float4* A4 = (const float4*)A;
    const float4* W4 = (const float4*)W;

    for (int k0 = 0; k0 < DIM; k0 += 32) {
        // A tile: 128 rows x 32 k  (1024 float4), stored transposed As[k][m]
#pragma unroll
        for (int it = 0; it < 4; it++) {
            int idx4 = tid + it * 256;
            int row  = idx4 >> 3;
            int kk   = idx4 & 7;
            int rg   = m0 + row; if (rg >= M) rg = M - 1;   // clamp (stores guarded)
            float4 f = A4[rg * DIM4 + (k0 >> 2) + kk];
            As[(kk * 4 + 0) * 128 + row] = f.x;
            As[(kk * 4 + 1) * 128 + row] = f.y;
            As[(kk * 4 + 2) * 128 + row] = f.z;
            As[(kk * 4 + 3) * 128 + row] = f.w;
        }
        // W tile: rows k0..k0+31, contiguous copy
#pragma unroll
        for (int it = 0; it < 4; it++) {
            int idx4 = tid + it * 256;
            ((float4*)Bs)[idx4] = W4[k0 * DIM4 + idx4];
        }
        __syncthreads();

#pragma unroll
        for (int k = 0; k < 32; k++) {
            float a[8], b[8];
            *(float4*)&a[0] = *(const float4*)&As[k * 128 + ty * 8];
            *(float4*)&a[4] = *(const float4*)&As[k * 128 + ty * 8 + 4];
            *(float4*)&b[0] = *(const float4*)&Bs[k * 128 + tx * 8];
            *(float4*)&b[4] = *(const float4*)&Bs[k * 128 + tx * 8 + 4];
#pragma unroll
            for (int i = 0; i < 8; i++)
#pragma unroll
                for (int j = 0; j < 8; j++)
                    acc[i][j] = fmaf(a[i], b[j], acc[i][j]);
        }
        __syncthreads();
    }

#pragma unroll
    for (int i = 0; i < 8; i++) {
        int rg = m0 + ty * 8 + i;
        if (rg < M) {
            float4 v0 = make_float4(acc[i][0], acc[i][1], acc[i][2], acc[i][3]);
            float4 v1 = make_float4(acc[i][4], acc[i][5], acc[i][6], acc[i][7]);
            float4* out4 = (float4*)g_support;
            out4[rg * DIM4 + tx * 2]     = v0;
            out4[rg * DIM4 + tx * 2 + 1] = v1;
        }
    }
}

// ---------------- 2. histogram of edge rows -------------------------------
__global__ void hist_kernel(const int* __restrict__ rows, int e) {
    int i = blockIdx.x * blockDim.x + threadIdx.x;
    if (i < e) atomicAdd(&g_count[rows[i]], 1);
}

// ---------------- 3. single-CTA exclusive scan -> rowptr/head -------------
__global__ __launch_bounds__(1024) void scan_kernel(int n) {
    __shared__ int sh[1024];
    const int tid = threadIdx.x;
    const int per = (n + 1023) >> 10;
    const int base = tid * per;

    int s = 0;
    for (int i = 0; i < per; i++) {
        int idx = base + i;
        if (idx < n) s += g_count[idx];
    }
    sh[tid] = s;
    __syncthreads();

    // Hillis–Steele inclusive scan over 1024 partials
    for (int off = 1; off < 1024; off <<= 1) {
        int v = (tid >= off) ? sh[tid - off] : 0;
        __syncthreads();
        sh[tid] += v;
        __syncthreads();
    }

    int run = (tid == 0) ? 0 : sh[tid - 1];
    for (int i = 0; i < per; i++) {
        int idx = base + i;
        if (idx < n) {
            g_rowptr[idx] = run;
            g_head[idx]   = run;
            run += g_count[idx];
        }
    }
    if (tid == 0) g_rowptr[n] = sh[1023];
}

// ---------------- 4. scatter edges into CSR order -------------------------
__global__ void scatter_kernel(const int* __restrict__ rows,
                               const int* __restrict__ cols,
                               const float* __restrict__ vals, int e) {
    int i = blockIdx.x * blockDim.x + threadIdx.x;
    if (i < e) {
        int pos = atomicAdd(&g_head[rows[i]], 1);
        g_col[pos] = cols[i];
        g_val[pos] = vals[i];
    }
}

// ---------------- 5. fused gather + blend + L2-normalize + bias ----------
// One warp per output row; each lane owns 4 consecutive columns (float4).
__global__ __launch_bounds__(256) void agg_kernel(
    const float* __restrict__ input,
    const float* __restrict__ bias,
    float* __restrict__ out, int n)
{
    const int gtid = blockIdx.x * blockDim.x + threadIdx.x;
    const int row  = gtid >> 5;
    const int lane = gtid & 31;
    if (row >= n) return;

    const int start = g_rowptr[row];
    const int end   = g_rowptr[row + 1];

    const float4* sup4 = (const float4*)g_support;
    float4 acc = make_float4(0.f, 0.f, 0.f, 0.f);

    for (int e0 = start; e0 < end; e0 += 32) {
        int   e = e0 + lane;
        int   c = (e < end) ? g_col[e] : 0;
        float v = (e < end) ? g_val[e] : 0.f;
        int cnt = min(32, end - e0);
        for (int j = 0; j < cnt; j++) {
            int   cj = __shfl_sync(0xffffffffu, c, j);
            float vj = __shfl_sync(0xffffffffu, v, j);
            float4 s = sup4[cj * DIM4 + lane];
            acc.x = fmaf(vj, s.x, acc.x);
            acc.y = fmaf(vj, s.y, acc.y);
            acc.z = fmaf(vj, s.z, acc.z);
            acc.w = fmaf(vj, s.w, acc.w);
        }
    }

    float4 in4 = ((const float4*)input)[row * DIM4 + lane];
    float4 o;
    o.x = fmaf(BETA, in4.x, ONE_MB * acc.x);
    o.y = fmaf(BETA, in4.y, ONE_MB * acc.y);
    o.z = fmaf(BETA, in4.z, ONE_MB * acc.z);
    o.w = fmaf(BETA, in4.w, ONE_MB * acc.w);

    float ss = o.x * o.x + o.y * o.y + o.z * o.z + o.w * o.w;
#pragma unroll
    for (int off = 16; off; off >>= 1)
        ss += __shfl_xor_sync(0xffffffffu, ss, off);

    float inv = 1.f / fmaxf(sqrtf(ss), EPS_NORM);

    float4 b4 = ((const float4*)bias)[lane];
    o.x = fmaf(o.x, inv, b4.x);
    o.y = fmaf(o.y, inv, b4.y);
    o.z = fmaf(o.z, inv, b4.z);
    o.w = fmaf(o.w, inv, b4.w);

    ((float4*)out)[row * DIM4 + lane] = o;
}

// ---------------- launch ---------------------------------------------------
extern "C" void kernel_launch(void* const* d_in, const int* in_sizes, int n_in,
                              void* d_out, int out_size) {
    const float* input     = (const float*)d_in[0];
    const int*   edge_rows = (const int*)  d_in[1];
    const int*   edge_cols = (const int*)  d_in[2];
    const float* edge_vals = (const float*)d_in[3];
    const float* weight    = (const float*)d_in[4];
    const float* bias      = (const float*)d_in[5];
    float*       out       = (float*)d_out;

    const int n = in_sizes[0] / DIM;   // 100000
    const int e = in_sizes[1];         // 1600000

    zero_count_kernel<<<(n + 255) / 256, 256>>>(n);
    gemm_kernel<<<(n + 127) / 128, 256>>>(input, weight, n);
    hist_kernel<<<(e + 255) / 256, 256>>>(edge_rows, e);
    scan_kernel<<<1, 1024>>>(n);
    scatter_kernel<<<(e + 255) / 256, 256>>>(edge_rows, edge_cols, edge_vals, e);
    agg_kernel<<<((long long)n * 32 + 255) / 256, 256>>>(input, bias, out, n);
}

// round 5
// speedup vs baseline: 1.6852x; 1.6852x over previous
#include <cuda_runtime.h>
#include <math.h>

#define DIM      128
#define DIM4     32          // DIM / 4
#define MAXN     100000
#define MAXE     1600000
#define BETA     0.001f
#define ONE_MB   0.999f      // 1 - BETA
#define EPS_NORM 1e-12f

#define SCAN_B   1024                         // elements per scan block
#define NBLK(n)  (((n) + SCAN_B - 1) / SCAN_B)

// ---------------- device scratch (no allocations allowed) ----------------
__device__ float g_support[(size_t)MAXN * DIM];   // 51.2 MB, L2-resident
__device__ int   g_count [MAXN];
__device__ int   g_rowptr[MAXN + 1];
__device__ int   g_head  [MAXN];
__device__ int   g_col   [MAXE];
__device__ float g_val   [MAXE];
__device__ int   g_bsum  [128];                   // block sums (<=98 used)

// ---------------- 0. zero the per-row edge counters ----------------------
__global__ void zero_count_kernel(int n) {
    int i = blockIdx.x * blockDim.x + threadIdx.x;
    if (i < n) g_count[i] = 0;
}

// ---------------- 1. support = input @ W  (fp32 SIMT GEMM) ---------------
// BM=128 rows per CTA, full N=128 cols, BK=32, 256 threads, 8x8 microtile.
__global__ __launch_bounds__(256) void gemm_kernel(
    const float* __restrict__ A,   // [M, 128]
    const float* __restrict__ W,   // [128, 128]
    int M)
{
    __shared__ float As[32 * 128];   // As[k][m]
    __shared__ float Bs[32 * 128];   // Bs[k][n]

    const int tid = threadIdx.x;
    const int tx  = tid & 15;
    const int ty  = tid >> 4;
    const int m0  = blockIdx.x * 128;

    float acc[8][8];
#pragma unroll
    for (int i = 0; i < 8; i++)
#pragma unroll
        for (int j = 0; j < 8; j++) acc[i][j] = 0.f;

    const float4* A4 = (const float4*)A;
    const float4* W4 = (const float4*)W;

    for (int k0 = 0; k0 < DIM; k0 += 32) {
        // A tile: 128 rows x 32 k  (1024 float4), stored transposed As[k][m]
#pragma unroll
        for (int it = 0; it < 4; it++) {
            int idx4 = tid + it * 256;
            int row  = idx4 >> 3;
            int kk   = idx4 & 7;
            int rg   = m0 + row; if (rg >= M) rg = M - 1;   // clamp (stores guarded)
            float4 f = A4[rg * DIM4 + (k0 >> 2) + kk];
            As[(kk * 4 + 0) * 128 + row] = f.x;
            As[(kk * 4 + 1) * 128 + row] = f.y;
            As[(kk * 4 + 2) * 128 + row] = f.z;
            As[(kk * 4 + 3) * 128 + row] = f.w;
        }
        // W tile: rows k0..k0+31, contiguous copy
#pragma unroll
        for (int it = 0; it < 4; it++) {
            int idx4 = tid + it * 256;
            ((float4*)Bs)[idx4] = W4[k0 * DIM4 + idx4];
        }
        __syncthreads();

#pragma unroll
        for (int k = 0; k < 32; k++) {
            float a[8], b[8];
            *(float4*)&a[0] = *(const float4*)&As[k * 128 + ty * 8];
            *(float4*)&a[4] = *(const float4*)&As[k * 128 + ty * 8 + 4];
            *(float4*)&b[0] = *(const float4*)&Bs[k * 128 + tx * 8];
            *(float4*)&b[4] = *(const float4*)&Bs[k * 128 + tx * 8 + 4];
#pragma unroll
            for (int i = 0; i < 8; i++)
#pragma unroll
                for (int j = 0; j < 8; j++)
                    acc[i][j] = fmaf(a[i], b[j], acc[i][j]);
        }
        __syncthreads();
    }

#pragma unroll
    for (int i = 0; i < 8; i++) {
        int rg = m0 + ty * 8 + i;
        if (rg < M) {
            float4 v0 = make_float4(acc[i][0], acc[i][1], acc[i][2], acc[i][3]);
            float4 v1 = make_float4(acc[i][4], acc[i][5], acc[i][6], acc[i][7]);
            float4* out4 = (float4*)g_support;
            out4[rg * DIM4 + tx * 2]     = v0;
            out4[rg * DIM4 + tx * 2 + 1] = v1;
        }
    }
}

// ---------------- 2. histogram of edge rows -------------------------------
__global__ void hist_kernel(const int* __restrict__ rows, int e) {
    int i = blockIdx.x * blockDim.x + threadIdx.x;
    if (i < e) atomicAdd(&g_count[rows[i]], 1);
}

// ---------------- 3a. per-block local exclusive scan ----------------------
__global__ __launch_bounds__(SCAN_B) void scan1_kernel(int n) {
    __shared__ int sh[SCAN_B];
    const int tid = threadIdx.x;
    const int idx = blockIdx.x * SCAN_B + tid;

    int v = (idx < n) ? g_count[idx] : 0;
    sh[tid] = v;
    __syncthreads();

#pragma unroll
    for (int off = 1; off < SCAN_B; off <<= 1) {
        int t = (tid >= off) ? sh[tid - off] : 0;
        __syncthreads();
        sh[tid] += t;
        __syncthreads();
    }

    if (idx < n) g_rowptr[idx] = sh[tid] - v;        // local exclusive
    if (tid == SCAN_B - 1) g_bsum[blockIdx.x] = sh[SCAN_B - 1];
}

// ---------------- 3b. scan of block sums (1 CTA, <=128 blocks) ------------
__global__ __launch_bounds__(128) void scan2_kernel(int nblk, int n) {
    __shared__ int sh[128];
    const int tid = threadIdx.x;
    int v = (tid < nblk) ? g_bsum[tid] : 0;
    sh[tid] = v;
    __syncthreads();

#pragma unroll
    for (int off = 1; off < 128; off <<= 1) {
        int t = (tid >= off) ? sh[tid - off] : 0;
        __syncthreads();
        sh[tid] += t;
        __syncthreads();
    }

    if (tid < nblk) g_bsum[tid] = sh[tid] - v;       // exclusive block offsets
    if (tid == 127) g_rowptr[n] = sh[127];           // grand total
}

// ---------------- 3c. add block offsets, materialize head -----------------
__global__ __launch_bounds__(SCAN_B) void scan3_kernel(int n) {
    const int idx = blockIdx.x * SCAN_B + threadIdx.x;
    if (idx < n) {
        int r = g_rowptr[idx] + g_bsum[blockIdx.x];
        g_rowptr[idx] = r;
        g_head[idx]   = r;
    }
}

// ---------------- 4. scatter edges into CSR order -------------------------
__global__ void scatter_kernel(const int* __restrict__ rows,
                               const int* __restrict__ cols,
                               const float* __restrict__ vals, int e) {
    int i = blockIdx.x * blockDim.x + threadIdx.x;
    if (i < e) {
        int pos = atomicAdd(&g_head[rows[i]], 1);
        g_col[pos] = cols[i];
        g_val[pos] = vals[i];
    }
}

// ---------------- 5. fused gather + blend + L2-normalize + bias ----------
// One warp per output row; each lane owns 4 consecutive columns (float4).
__global__ __launch_bounds__(256) void agg_kernel(
    const float* __restrict__ input,
    const float* __restrict__ bias,
    float* __restrict__ out, int n)
{
    const int gtid = blockIdx.x * blockDim.x + threadIdx.x;
    const int row  = gtid >> 5;
    const int lane = gtid & 31;
    if (row >= n) return;

    const int start = g_rowptr[row];
    const int end   = g_rowptr[row + 1];

    const float4* sup4 = (const float4*)g_support;
    float4 acc = make_float4(0.f, 0.f, 0.f, 0.f);

    for (int e0 = start; e0 < end; e0 += 32) {
        int   e = e0 + lane;
        int   c = (e < end) ? g_col[e] : 0;
        float v = (e < end) ? g_val[e] : 0.f;
        int cnt = min(32, end - e0);
        for (int j = 0; j < cnt; j++) {
            int   cj = __shfl_sync(0xffffffffu, c, j);
            float vj = __shfl_sync(0xffffffffu, v, j);
            float4 s = sup4[cj * DIM4 + lane];
            acc.x = fmaf(vj, s.x, acc.x);
            acc.y = fmaf(vj, s.y, acc.y);
            acc.z = fmaf(vj, s.z, acc.z);
            acc.w = fmaf(vj, s.w, acc.w);
        }
    }

    float4 in4 = ((const float4*)input)[row * DIM4 + lane];
    float4 o;
    o.x = fmaf(BETA, in4.x, ONE_MB * acc.x);
    o.y = fmaf(BETA, in4.y, ONE_MB * acc.y);
    o.z = fmaf(BETA, in4.z, ONE_MB * acc.z);
    o.w = fmaf(BETA, in4.w, ONE_MB * acc.w);

    float ss = o.x * o.x + o.y * o.y + o.z * o.z + o.w * o.w;
#pragma unroll
    for (int off = 16; off; off >>= 1)
        ss += __shfl_xor_sync(0xffffffffu, ss, off);

    float inv = 1.f / fmaxf(sqrtf(ss), EPS_NORM);

    float4 b4 = ((const float4*)bias)[lane];
    o.x = fmaf(o.x, inv, b4.x);
    o.y = fmaf(o.y, inv, b4.y);
    o.z = fmaf(o.z, inv, b4.z);
    o.w = fmaf(o.w, inv, b4.w);

    ((float4*)out)[row * DIM4 + lane] = o;
}

// ---------------- launch ---------------------------------------------------
extern "C" void kernel_launch(void* const* d_in, const int* in_sizes, int n_in,
                              void* d_out, int out_size) {
    const float* input     = (const float*)d_in[0];
    const int*   edge_rows = (const int*)  d_in[1];
    const int*   edge_cols = (const int*)  d_in[2];
    const float* edge_vals = (const float*)d_in[3];
    const float* weight    = (const float*)d_in[4];
    const float* bias      = (const float*)d_in[5];
    float*       out       = (float*)d_out;

    const int n = in_sizes[0] / DIM;   // 100000
    const int e = in_sizes[1];         // 1600000
    const int nblk = NBLK(n);          // 98

    zero_count_kernel<<<(n + 255) / 256, 256>>>(n);
    gemm_kernel<<<(n + 127) / 128, 256>>>(input, weight, n);
    hist_kernel<<<(e + 255) / 256, 256>>>(edge_rows, e);
    scan1_kernel<<<nblk, SCAN_B>>>(n);
    scan2_kernel<<<1, 128>>>(nblk, n);
    scan3_kernel<<<nblk, SCAN_B>>>(n);
    scatter_kernel<<<(e + 255) / 256, 256>>>(edge_rows, edge_cols, edge_vals, e);
    agg_kernel<<<((long long)n * 32 + 255) / 256, 256>>>(input, bias, out, n);
}

// round 6
// speedup vs baseline: 1.9958x; 1.1843x over previous
#include <cuda_runtime.h>
#include <cuda_fp16.h>
#include <math.h>

#define DIM      128
#define DIM4     32          // DIM / 4
#define MAXN     100000
#define MAXE     1600000
#define BETA     0.001f
#define ONE_MB   0.999f      // 1 - BETA
#define EPS_NORM 1e-12f

#define SCAN_B   1024                         // elements per scan block
#define NBLK(n)  (((n) + SCAN_B - 1) / SCAN_B)

// ---------------- device scratch (no allocations allowed) ----------------
__device__ __half g_support[(size_t)MAXN * DIM];  // 25.6 MB, L2-resident
__device__ int    g_count [MAXN];
__device__ int    g_rowptr[MAXN + 1];
__device__ int    g_head  [MAXN];
__device__ int    g_col   [MAXE];
__device__ float  g_val   [MAXE];
__device__ int    g_bsum  [128];                  // block sums (<=98 used)

// ---------------- 0. zero the per-row edge counters ----------------------
__global__ void zero_count_kernel(int n) {
    int i = blockIdx.x * blockDim.x + threadIdx.x;
    if (i < n) g_count[i] = 0;
}

// ---------------- 1. support = input @ W  (fp32 SIMT GEMM, fp16 store) ---
// BM=128 rows per CTA, full N=128 cols, BK=32, 256 threads, 8x8 microtile.
__global__ __launch_bounds__(256) void gemm_kernel(
    const float* __restrict__ A,   // [M, 128]
    const float* __restrict__ W,   // [128, 128]
    int M)
{
    __shared__ float As[32 * 128];   // As[k][m]
    __shared__ float Bs[32 * 128];   // Bs[k][n]

    const int tid = threadIdx.x;
    const int tx  = tid & 15;
    const int ty  = tid >> 4;
    const int m0  = blockIdx.x * 128;

    float acc[8][8];
#pragma unroll
    for (int i = 0; i < 8; i++)
#pragma unroll
        for (int j = 0; j < 8; j++) acc[i][j] = 0.f;

    const float4* A4 = (const float4*)A;
    const float4* W4 = (const float4*)W;

    for (int k0 = 0; k0 < DIM; k0 += 32) {
        // A tile: 128 rows x 32 k  (1024 float4), stored transposed As[k][m]
#pragma unroll
        for (int it = 0; it < 4; it++) {
            int idx4 = tid + it * 256;
            int row  = idx4 >> 3;
            int kk   = idx4 & 7;
            int rg   = m0 + row; if (rg >= M) rg = M - 1;   // clamp (stores guarded)
            float4 f = A4[rg * DIM4 + (k0 >> 2) + kk];
            As[(kk * 4 + 0) * 128 + row] = f.x;
            As[(kk * 4 + 1) * 128 + row] = f.y;
            As[(kk * 4 + 2) * 128 + row] = f.z;
            As[(kk * 4 + 3) * 128 + row] = f.w;
        }
        // W tile: rows k0..k0+31, contiguous copy
#pragma unroll
        for (int it = 0; it < 4; it++) {
            int idx4 = tid + it * 256;
            ((float4*)Bs)[idx4] = W4[k0 * DIM4 + idx4];
        }
        __syncthreads();

#pragma unroll
        for (int k = 0; k < 32; k++) {
            float a[8], b[8];
            *(float4*)&a[0] = *(const float4*)&As[k * 128 + ty * 8];
            *(float4*)&a[4] = *(const float4*)&As[k * 128 + ty * 8 + 4];
            *(float4*)&b[0] = *(const float4*)&Bs[k * 128 + tx * 8];
            *(float4*)&b[4] = *(const float4*)&Bs[k * 128 + tx * 8 + 4];
#pragma unroll
            for (int i = 0; i < 8; i++)
#pragma unroll
                for (int j = 0; j < 8; j++)
                    acc[i][j] = fmaf(a[i], b[j], acc[i][j]);
        }
        __syncthreads();
    }

    // Epilogue: convert each thread's 8 contiguous columns to fp16 (16B store)
#pragma unroll
    for (int i = 0; i < 8; i++) {
        int rg = m0 + ty * 8 + i;
        if (rg < M) {
            __half2 h[4];
#pragma unroll
            for (int j = 0; j < 4; j++)
                h[j] = __floats2half2_rn(acc[i][2 * j], acc[i][2 * j + 1]);
            // row rg, cols tx*8 .. tx*8+7  ->  8 halves = 16 bytes, aligned
            ((uint4*)g_support)[rg * (DIM / 8) + tx] = *(uint4*)h;
        }
    }
}

// ---------------- 2. histogram of edge rows -------------------------------
__global__ void hist_kernel(const int* __restrict__ rows, int e) {
    int i = blockIdx.x * blockDim.x + threadIdx.x;
    if (i < e) atomicAdd(&g_count[rows[i]], 1);
}

// ---------------- 3a. per-block local exclusive scan ----------------------
__global__ __launch_bounds__(SCAN_B) void scan1_kernel(int n) {
    __shared__ int sh[SCAN_B];
    const int tid = threadIdx.x;
    const int idx = blockIdx.x * SCAN_B + tid;

    int v = (idx < n) ? g_count[idx] : 0;
    sh[tid] = v;
    __syncthreads();

#pragma unroll
    for (int off = 1; off < SCAN_B; off <<= 1) {
        int t = (tid >= off) ? sh[tid - off] : 0;
        __syncthreads();
        sh[tid] += t;
        __syncthreads();
    }

    if (idx < n) g_rowptr[idx] = sh[tid] - v;        // local exclusive
    if (tid == SCAN_B - 1) g_bsum[blockIdx.x] = sh[SCAN_B - 1];
}

// ---------------- 3b. scan of block sums (1 CTA, <=128 blocks) ------------
__global__ __launch_bounds__(128) void scan2_kernel(int nblk, int n) {
    __shared__ int sh[128];
    const int tid = threadIdx.x;
    int v = (tid < nblk) ? g_bsum[tid] : 0;
    sh[tid] = v;
    __syncthreads();

#pragma unroll
    for (int off = 1; off < 128; off <<= 1) {
        int t = (tid >= off) ? sh[tid - off] : 0;
        __syncthreads();
        sh[tid] += t;
        __syncthreads();
    }

    if (tid < nblk) g_bsum[tid] = sh[tid] - v;       // exclusive block offsets
    if (tid == 127) g_rowptr[n] = sh[127];           // grand total
}

// ---------------- 3c. add block offsets, materialize head -----------------
__global__ __launch_bounds__(SCAN_B) void scan3_kernel(int n) {
    const int idx = blockIdx.x * SCAN_B + threadIdx.x;
    if (idx < n) {
        int r = g_rowptr[idx] + g_bsum[blockIdx.x];
        g_rowptr[idx] = r;
        g_head[idx]   = r;
    }
}

// ---------------- 4. scatter edges into CSR order -------------------------
__global__ void scatter_kernel(const int* __restrict__ rows,
                               const int* __restrict__ cols,
                               const float* __restrict__ vals, int e) {
    int i = blockIdx.x * blockDim.x + threadIdx.x;
    if (i < e) {
        int pos = atomicAdd(&g_head[rows[i]], 1);
        g_col[pos] = cols[i];
        g_val[pos] = vals[i];
    }
}

// ---------------- 5. fused gather + blend + L2-normalize + bias ----------
// One warp per output row; each lane owns 4 consecutive columns (8B fp16).
__global__ __launch_bounds__(256) void agg_kernel(
    const float* __restrict__ input,
    const float* __restrict__ bias,
    float* __restrict__ out, int n)
{
    const int gtid = blockIdx.x * blockDim.x + threadIdx.x;
    const int row  = gtid >> 5;
    const int lane = gtid & 31;
    if (row >= n) return;

    const int start = g_rowptr[row];
    const int end   = g_rowptr[row + 1];

    const uint2* sup8 = (const uint2*)g_support;   // 4 halves per uint2
    float4 acc = make_float4(0.f, 0.f, 0.f, 0.f);

    for (int e0 = start; e0 < end; e0 += 32) {
        int   e = e0 + lane;
        int   c = (e < end) ? g_col[e] : 0;
        float v = (e < end) ? g_val[e] : 0.f;
        int cnt = min(32, end - e0);
        for (int j = 0; j < cnt; j++) {
            int   cj = __shfl_sync(0xffffffffu, c, j);
            float vj = __shfl_sync(0xffffffffu, v, j);
            uint2 u  = sup8[cj * DIM4 + lane];     // row cj, cols lane*4..+3
            float2 s0 = __half22float2(*(__half2*)&u.x);
            float2 s1 = __half22float2(*(__half2*)&u.y);
            acc.x = fmaf(vj, s0.x, acc.x);
            acc.y = fmaf(vj, s0.y, acc.y);
            acc.z = fmaf(vj, s1.x, acc.z);
            acc.w = fmaf(vj, s1.y, acc.w);
        }
    }

    float4 in4 = ((const float4*)input)[row * DIM4 + lane];
    float4 o;
    o.x = fmaf(BETA, in4.x, ONE_MB * acc.x);
    o.y = fmaf(BETA, in4.y, ONE_MB * acc.y);
    o.z = fmaf(BETA, in4.z, ONE_MB * acc.z);
    o.w = fmaf(BETA, in4.w, ONE_MB * acc.w);

    float ss = o.x * o.x + o.y * o.y + o.z * o.z + o.w * o.w;
#pragma unroll
    for (int off = 16; off; off >>= 1)
        ss += __shfl_xor_sync(0xffffffffu, ss, off);

    float inv = 1.f / fmaxf(sqrtf(ss), EPS_NORM);

    float4 b4 = ((const float4*)bias)[lane];
    o.x = fmaf(o.x, inv, b4.x);
    o.y = fmaf(o.y, inv, b4.y);
    o.z = fmaf(o.z, inv, b4.z);
    o.w = fmaf(o.w, inv, b4.w);

    ((float4*)out)[row * DIM4 + lane] = o;
}

// ---------------- launch ---------------------------------------------------
extern "C" void kernel_launch(void* const* d_in, const int* in_sizes, int n_in,
                              void* d_out, int out_size) {
    const float* input     = (const float*)d_in[0];
    const int*   edge_rows = (const int*)  d_in[1];
    const int*   edge_cols = (const int*)  d_in[2];
    const float* edge_vals = (const float*)d_in[3];
    const float* weight    = (const float*)d_in[4];
    const float* bias      = (const float*)d_in[5];
    float*       out       = (float*)d_out;

    const int n = in_sizes[0] / DIM;   // 100000
    const int e = in_sizes[1];         // 1600000
    const int nblk = NBLK(n);          // 98

    zero_count_kernel<<<(n + 255) / 256, 256>>>(n);
    gemm_kernel<<<(n + 127) / 128, 256>>>(input, weight, n);
    hist_kernel<<<(e + 255) / 256, 256>>>(edge_rows, e);
    scan1_kernel<<<nblk, SCAN_B>>>(n);
    scan2_kernel<<<1, 128>>>(nblk, n);
    scan3_kernel<<<nblk, SCAN_B>>>(n);
    scatter_kernel<<<(e + 255) / 256, 256>>>(edge_rows, edge_cols, edge_vals, e);
    agg_kernel<<<((long long)n * 32 + 255) / 256, 256>>>(input, bias, out, n);
}

// round 7
// speedup vs baseline: 2.8216x; 1.4138x over previous
#include <cuda_runtime.h>
#include <cuda_fp16.h>
#include <math.h>
#include <stdint.h>

#define DIM      128
#define DIM4     32          // DIM / 4
#define MAXN     100000
#define MAXE     1600000
#define BETA     0.001f
#define ONE_MB   0.999f      // 1 - BETA
#define EPS_NORM 1e-12f

#define SCAN_B   1024
#define NBLK(n)  (((n) + SCAN_B - 1) / SCAN_B)

#define BK        64                 // K elements per smem pass
#define AS_STRIDE (BK + 8)           // 72 halves = 144B row stride (9x16B, conflict-free)

// ---------------- device scratch (no allocations allowed) ----------------
__device__ __half g_support[(size_t)MAXN * DIM];  // 25.6 MB, L2-resident
__device__ __half g_wt[DIM * DIM];                // W^T, [n][k] fp16
__device__ int    g_count [MAXN];
__device__ int    g_rowptr[MAXN + 1];
__device__ int    g_head  [MAXN];
__device__ int    g_col   [MAXE];
__device__ float  g_val   [MAXE];
__device__ int    g_bsum  [128];

// ---------------- PTX helpers ---------------------------------------------
__device__ __forceinline__ uint32_t smem_u32(const void* p) {
    return (uint32_t)__cvta_generic_to_shared(p);
}
__device__ __forceinline__ void ldm_x4(uint32_t& r0, uint32_t& r1,
                                       uint32_t& r2, uint32_t& r3, uint32_t addr) {
    asm volatile("ldmatrix.sync.aligned.m8n8.x4.shared.b16 {%0,%1,%2,%3}, [%4];"
        : "=r"(r0), "=r"(r1), "=r"(r2), "=r"(r3) : "r"(addr));
}
__device__ __forceinline__ void mma16816(float* c, const uint32_t* a, const uint32_t* b) {
    asm volatile("mma.sync.aligned.m16n8k16.row.col.f32.f16.f16.f32 "
        "{%0,%1,%2,%3}, {%4,%5,%6,%7}, {%8,%9}, {%0,%1,%2,%3};"
        : "+f"(c[0]), "+f"(c[1]), "+f"(c[2]), "+f"(c[3])
        : "r"(a[0]), "r"(a[1]), "r"(a[2]), "r"(a[3]), "r"(b[0]), "r"(b[1]));
}

// ---------------- 0. zero the per-row edge counters ----------------------
__global__ void zero_count_kernel(int n) {
    int i = blockIdx.x * blockDim.x + threadIdx.x;
    if (i < n) g_count[i] = 0;
}

// ---------------- 0b. W [k][n] fp32 -> g_wt [n][k] fp16 -------------------
__global__ void wt_kernel(const float* __restrict__ W) {
    int tid = blockIdx.x * blockDim.x + threadIdx.x;
    if (tid < DIM * DIM) {
        int n = tid >> 7, k = tid & 127;
        g_wt[n * DIM + k] = __float2half_rn(W[k * DIM + n]);
    }
}

// ---------------- 1. support = input @ W  (HMMA fp16, fp32 accum) --------
// CTA: 128 M x 128 N, 8 warps as 2(M) x 4(N): warp tile 64M x 32N.
// Two K passes of BK=64 through smem; ldmatrix + mma.m16n8k16.
__global__ __launch_bounds__(256) void gemm_hmma_kernel(
    const float* __restrict__ A, int M)
{
    __shared__ __half As[128 * AS_STRIDE];   // [m][k_local]
    __shared__ __half Ws[128 * AS_STRIDE];   // [n][k_local]

    const int tid  = threadIdx.x;
    const int warp = tid >> 5;
    const int lane = tid & 31;
    const int m0   = blockIdx.x * 128;

    const int wm = warp & 1;          // 2 warps along M
    const int wn = warp >> 1;         // 4 warps along N
    const int mbase = wm * 64;        // 4 m16 tiles per warp
    const int nbase = wn * 32;        // 4 n8  tiles per warp

    float acc[4][4][4];
#pragma unroll
    for (int i = 0; i < 4; i++)
#pragma unroll
        for (int j = 0; j < 4; j++)
#pragma unroll
            for (int q = 0; q < 4; q++) acc[i][j][q] = 0.f;

    const float4* A4 = (const float4*)A;
    const uint32_t as_base = smem_u32(As);
    const uint32_t ws_base = smem_u32(Ws);

    // ldmatrix lane geometry (shared by A and B tiles)
    const int mat = lane >> 3;        // which 8x8 matrix this lane addresses
    const int rin = lane & 7;         // row within the matrix
    const int rofs = rin + (mat & 1) * 8;       // row offset within 16
    const int kofs = (mat >> 1) * 8;            // k offset within 16

    for (int pass = 0; pass < 2; pass++) {
        const int kg = pass * BK;     // global k base of this pass

        // --- stage A: 128 rows x 64 k  (fp32 -> fp16), 8 float4/thread ---
#pragma unroll
        for (int it = 0; it < 8; it++) {
            int idx4 = tid + it * 256;          // 0..2047
            int row  = idx4 >> 4;               // 16 float4 per row
            int c4   = idx4 & 15;
            int rg   = m0 + row; if (rg >= M) rg = M - 1;
            float4 f = A4[(size_t)rg * DIM4 + (kg >> 2) + c4];
            __half2* dst = (__half2*)&As[row * AS_STRIDE + c4 * 4];
            dst[0] = __floats2half2_rn(f.x, f.y);
            dst[1] = __floats2half2_rn(f.z, f.w);
        }
        // --- stage W^T: 128 n-rows x 64 k halves, 4 uint4/thread ---------
#pragma unroll
        for (int it = 0; it < 4; it++) {
            int idx8 = tid + it * 256;          // 0..1023
            int row  = idx8 >> 3;               // 8 uint4 per row
            int c8   = idx8 & 7;
            uint4 u = *(const uint4*)&g_wt[row * DIM + kg + c8 * 8];
            *(uint4*)&Ws[row * AS_STRIDE + c8 * 8] = u;
        }
        __syncthreads();

#pragma unroll
        for (int ks = 0; ks < BK / 16; ks++) {
            const int k0 = ks * 16;

            uint32_t a[4][4];
#pragma unroll
            for (int mt = 0; mt < 4; mt++) {
                uint32_t addr = as_base +
                    ((mbase + mt * 16 + rofs) * AS_STRIDE + k0 + kofs) * 2;
                ldm_x4(a[mt][0], a[mt][1], a[mt][2], a[mt][3], addr);
            }
            uint32_t b[4][2];
#pragma unroll
            for (int g = 0; g < 2; g++) {
                uint32_t addr = ws_base +
                    ((nbase + g * 16 + rofs) * AS_STRIDE + k0 + kofs) * 2;
                uint32_t r0, r1, r2, r3;
                ldm_x4(r0, r1, r2, r3, addr);
                b[g * 2 + 0][0] = r0; b[g * 2 + 0][1] = r2;
                b[g * 2 + 1][0] = r1; b[g * 2 + 1][1] = r3;
            }
#pragma unroll
            for (int mt = 0; mt < 4; mt++)
#pragma unroll
                for (int nt = 0; nt < 4; nt++)
                    mma16816(acc[mt][nt], a[mt], b[nt]);
        }
        __syncthreads();
    }

    // --- epilogue: fp32 acc -> fp16 half2 stores to g_support ------------
#pragma unroll
    for (int mt = 0; mt < 4; mt++) {
        int m1 = m0 + mbase + mt * 16 + (lane >> 2);
        int m2 = m1 + 8;
#pragma unroll
        for (int nt = 0; nt < 4; nt++) {
            int nc = nbase + nt * 8 + (lane & 3) * 2;
            if (m1 < M)
                *(__half2*)&g_support[(size_t)m1 * DIM + nc] =
                    __floats2half2_rn(acc[mt][nt][0], acc[mt][nt][1]);
            if (m2 < M)
                *(__half2*)&g_support[(size_t)m2 * DIM + nc] =
                    __floats2half2_rn(acc[mt][nt][2], acc[mt][nt][3]);
        }
    }
}

// ---------------- 2. histogram of edge rows -------------------------------
__global__ void hist_kernel(const int* __restrict__ rows, int e) {
    int i = blockIdx.x * blockDim.x + threadIdx.x;
    if (i < e) atomicAdd(&g_count[rows[i]], 1);
}

// ---------------- 3a. per-block local exclusive scan ----------------------
__global__ __launch_bounds__(SCAN_B) void scan1_kernel(int n) {
    __shared__ int sh[SCAN_B];
    const int tid = threadIdx.x;
    const int idx = blockIdx.x * SCAN_B + tid;

    int v = (idx < n) ? g_count[idx] : 0;
    sh[tid] = v;
    __syncthreads();

#pragma unroll
    for (int off = 1; off < SCAN_B; off <<= 1) {
        int t = (tid >= off) ? sh[tid - off] : 0;
        __syncthreads();
        sh[tid] += t;
        __syncthreads();
    }

    if (idx < n) g_rowptr[idx] = sh[tid] - v;
    if (tid == SCAN_B - 1) g_bsum[blockIdx.x] = sh[SCAN_B - 1];
}

// ---------------- 3b. scan of block sums (1 CTA) ---------------------------
__global__ __launch_bounds__(128) void scan2_kernel(int nblk, int n) {
    __shared__ int sh[128];
    const int tid = threadIdx.x;
    int v = (tid < nblk) ? g_bsum[tid] : 0;
    sh[tid] = v;
    __syncthreads();

#pragma unroll
    for (int off = 1; off < 128; off <<= 1) {
        int t = (tid >= off) ? sh[tid - off] : 0;
        __syncthreads();
        sh[tid] += t;
        __syncthreads();
    }

    if (tid < nblk) g_bsum[tid] = sh[tid] - v;
    if (tid == 127) g_rowptr[n] = sh[127];
}

// ---------------- 3c. add block offsets, materialize head -----------------
__global__ __launch_bounds__(SCAN_B) void scan3_kernel(int n) {
    const int idx = blockIdx.x * SCAN_B + threadIdx.x;
    if (idx < n) {
        int r = g_rowptr[idx] + g_bsum[blockIdx.x];
        g_rowptr[idx] = r;
        g_head[idx]   = r;
    }
}

// ---------------- 4. scatter edges into CSR order -------------------------
__global__ void scatter_kernel(const int* __restrict__ rows,
                               const int* __restrict__ cols,
                               const float* __restrict__ vals, int e) {
    int i = blockIdx.x * blockDim.x + threadIdx.x;
    if (i < e) {
        int pos = atomicAdd(&g_head[rows[i]], 1);
        g_col[pos] = cols[i];
        g_val[pos] = vals[i];
    }
}

// ---------------- 5. fused gather + blend + L2-normalize + bias ----------
__global__ __launch_bounds__(256) void agg_kernel(
    const float* __restrict__ input,
    const float* __restrict__ bias,
    float* __restrict__ out, int n)
{
    const int gtid = blockIdx.x * blockDim.x + threadIdx.x;
    const int row  = gtid >> 5;
    const int lane = gtid & 31;
    if (row >= n) return;

    const int start = g_rowptr[row];
    const int end   = g_rowptr[row + 1];

    const uint2* sup8 = (const uint2*)g_support;   // 4 halves per uint2
    float4 acc = make_float4(0.f, 0.f, 0.f, 0.f);

    for (int e0 = start; e0 < end; e0 += 32) {
        int   e = e0 + lane;
        int   c = (e < end) ? g_col[e] : 0;
        float v = (e < end) ? g_val[e] : 0.f;
        int cnt = min(32, end - e0);
        for (int j = 0; j < cnt; j++) {
            int   cj = __shfl_sync(0xffffffffu, c, j);
            float vj = __shfl_sync(0xffffffffu, v, j);
            uint2 u  = sup8[cj * DIM4 + lane];
            float2 s0 = __half22float2(*(__half2*)&u.x);
            float2 s1 = __half22float2(*(__half2*)&u.y);
            acc.x = fmaf(vj, s0.x, acc.x);
            acc.y = fmaf(vj, s0.y, acc.y);
            acc.z = fmaf(vj, s1.x, acc.z);
            acc.w = fmaf(vj, s1.y, acc.w);
        }
    }

    float4 in4 = ((const float4*)input)[row * DIM4 + lane];
    float4 o;
    o.x = fmaf(BETA, in4.x, ONE_MB * acc.x);
    o.y = fmaf(BETA, in4.y, ONE_MB * acc.y);
    o.z = fmaf(BETA, in4.z, ONE_MB * acc.z);
    o.w = fmaf(BETA, in4.w, ONE_MB * acc.w);

    float ss = o.x * o.x + o.y * o.y + o.z * o.z + o.w * o.w;
#pragma unroll
    for (int off = 16; off; off >>= 1)
        ss += __shfl_xor_sync(0xffffffffu, ss, off);

    float inv = 1.f / fmaxf(sqrtf(ss), EPS_NORM);

    float4 b4 = ((const float4*)bias)[lane];
    o.x = fmaf(o.x, inv, b4.x);
    o.y = fmaf(o.y, inv, b4.y);
    o.z = fmaf(o.z, inv, b4.z);
    o.w = fmaf(o.w, inv, b4.w);

    ((float4*)out)[row * DIM4 + lane] = o;
}

// ---------------- launch ---------------------------------------------------
extern "C" void kernel_launch(void* const* d_in, const int* in_sizes, int n_in,
                              void* d_out, int out_size) {
    const float* input     = (const float*)d_in[0];
    const int*   edge_rows = (const int*)  d_in[1];
    const int*   edge_cols = (const int*)  d_in[2];
    const float* edge_vals = (const float*)d_in[3];
    const float* weight    = (const float*)d_in[4];
    const float* bias      = (const float*)d_in[5];
    float*       out       = (float*)d_out;

    const int n = in_sizes[0] / DIM;   // 100000
    const int e = in_sizes[1];         // 1600000
    const int nblk = NBLK(n);          // 98

    zero_count_kernel<<<(n + 255) / 256, 256>>>(n);
    wt_kernel<<<(DIM * DIM + 255) / 256, 256>>>(weight);
    gemm_hmma_kernel<<<(n + 127) / 128, 256>>>(input, n);
    hist_kernel<<<(e + 255) / 256, 256>>>(edge_rows, e);
    scan1_kernel<<<nblk, SCAN_B>>>(n);
    scan2_kernel<<<1, 128>>>(nblk, n);
    scan3_kernel<<<nblk, SCAN_B>>>(n);
    scatter_kernel<<<(e + 255) / 256, 256>>>(edge_rows, edge_cols, edge_vals, e);
    agg_kernel<<<((long long)n * 32 + 255) / 256, 256>>>(input, bias, out, n);
}

// round 8
// speedup vs baseline: 3.0408x; 1.0777x over previous
#include <cuda_runtime.h>
#include <cuda_fp16.h>
#include <math.h>
#include <stdint.h>

#define DIM      128
#define DIM4     32          // DIM / 4
#define MAXN     100000
#define MAXE     1600000
#define BETA     0.001f
#define ONE_MB   0.999f      // 1 - BETA
#define EPS_NORM 1e-12f

#define SCAN_B   1024
#define NBLK(n)  (((n) + SCAN_B - 1) / SCAN_B)

#define BK        64                 // K elements per smem pass
#define AS_STRIDE (BK + 8)           // 72 halves = 144B row stride

// ---------------- device scratch (no allocations allowed) ----------------
__device__ __half g_support[(size_t)MAXN * DIM];  // 25.6 MB, L2-resident
__device__ __half g_wt[DIM * DIM];                // W^T, [n][k] fp16
__device__ int    g_count [MAXN];
__device__ int    g_rowptr[MAXN + 1];
__device__ int    g_head  [MAXN];
__device__ int2   g_edge  [MAXE];                 // packed (col, val-bits)
__device__ int    g_bsum  [128];

// ---------------- PTX helpers ---------------------------------------------
__device__ __forceinline__ uint32_t smem_u32(const void* p) {
    return (uint32_t)__cvta_generic_to_shared(p);
}
__device__ __forceinline__ void ldm_x4(uint32_t& r0, uint32_t& r1,
                                       uint32_t& r2, uint32_t& r3, uint32_t addr) {
    asm volatile("ldmatrix.sync.aligned.m8n8.x4.shared.b16 {%0,%1,%2,%3}, [%4];"
        : "=r"(r0), "=r"(r1), "=r"(r2), "=r"(r3) : "r"(addr));
}
__device__ __forceinline__ void mma16816(float* c, const uint32_t* a, const uint32_t* b) {
    asm volatile("mma.sync.aligned.m16n8k16.row.col.f32.f16.f16.f32 "
        "{%0,%1,%2,%3}, {%4,%5,%6,%7}, {%8,%9}, {%0,%1,%2,%3};"
        : "+f"(c[0]), "+f"(c[1]), "+f"(c[2]), "+f"(c[3])
        : "r"(a[0]), "r"(a[1]), "r"(a[2]), "r"(a[3]), "r"(b[0]), "r"(b[1]));
}

// ---------------- 0. zero the per-row edge counters ----------------------
__global__ void zero_count_kernel(int n) {
    int i = blockIdx.x * blockDim.x + threadIdx.x;
    if (i < n) g_count[i] = 0;
}

// ---------------- 0b. W [k][n] fp32 -> g_wt [n][k] fp16 -------------------
__global__ void wt_kernel(const float* __restrict__ W) {
    int tid = blockIdx.x * blockDim.x + threadIdx.x;
    if (tid < DIM * DIM) {
        int n = tid >> 7, k = tid & 127;
        g_wt[n * DIM + k] = __float2half_rn(W[k * DIM + n]);
    }
}

// ---------------- 1. support = input @ W  (HMMA fp16, fp32 accum) --------
__global__ __launch_bounds__(256) void gemm_hmma_kernel(
    const float* __restrict__ A, int M)
{
    __shared__ __half As[128 * AS_STRIDE];   // [m][k_local]
    __shared__ __half Ws[128 * AS_STRIDE];   // [n][k_local]

    const int tid  = threadIdx.x;
    const int warp = tid >> 5;
    const int lane = tid & 31;
    const int m0   = blockIdx.x * 128;

    const int wm = warp & 1;
    const int wn = warp >> 1;
    const int mbase = wm * 64;
    const int nbase = wn * 32;

    float acc[4][4][4];
#pragma unroll
    for (int i = 0; i < 4; i++)
#pragma unroll
        for (int j = 0; j < 4; j++)
#pragma unroll
            for (int q = 0; q < 4; q++) acc[i][j][q] = 0.f;

    const float4* A4 = (const float4*)A;
    const uint32_t as_base = smem_u32(As);
    const uint32_t ws_base = smem_u32(Ws);

    const int mat = lane >> 3;
    const int rin = lane & 7;
    const int rofs = rin + (mat & 1) * 8;
    const int kofs = (mat >> 1) * 8;

    for (int pass = 0; pass < 2; pass++) {
        const int kg = pass * BK;

#pragma unroll
        for (int it = 0; it < 8; it++) {
            int idx4 = tid + it * 256;
            int row  = idx4 >> 4;
            int c4   = idx4 & 15;
            int rg   = m0 + row; if (rg >= M) rg = M - 1;
            float4 f = A4[(size_t)rg * DIM4 + (kg >> 2) + c4];
            __half2* dst = (__half2*)&As[row * AS_STRIDE + c4 * 4];
            dst[0] = __floats2half2_rn(f.x, f.y);
            dst[1] = __floats2half2_rn(f.z, f.w);
        }
#pragma unroll
        for (int it = 0; it < 4; it++) {
            int idx8 = tid + it * 256;
            int row  = idx8 >> 3;
            int c8   = idx8 & 7;
            uint4 u = *(const uint4*)&g_wt[row * DIM + kg + c8 * 8];
            *(uint4*)&Ws[row * AS_STRIDE + c8 * 8] = u;
        }
        __syncthreads();

#pragma unroll
        for (int ks = 0; ks < BK / 16; ks++) {
            const int k0 = ks * 16;

            uint32_t a[4][4];
#pragma unroll
            for (int mt = 0; mt < 4; mt++) {
                uint32_t addr = as_base +
                    ((mbase + mt * 16 + rofs) * AS_STRIDE + k0 + kofs) * 2;
                ldm_x4(a[mt][0], a[mt][1], a[mt][2], a[mt][3], addr);
            }
            uint32_t b[4][2];
#pragma unroll
            for (int g = 0; g < 2; g++) {
                uint32_t addr = ws_base +
                    ((nbase + g * 16 + rofs) * AS_STRIDE + k0 + kofs) * 2;
                uint32_t r0, r1, r2, r3;
                ldm_x4(r0, r1, r2, r3, addr);
                b[g * 2 + 0][0] = r0; b[g * 2 + 0][1] = r2;
                b[g * 2 + 1][0] = r1; b[g * 2 + 1][1] = r3;
            }
#pragma unroll
            for (int mt = 0; mt < 4; mt++)
#pragma unroll
                for (int nt = 0; nt < 4; nt++)
                    mma16816(acc[mt][nt], a[mt], b[nt]);
        }
        __syncthreads();
    }

#pragma unroll
    for (int mt = 0; mt < 4; mt++) {
        int m1 = m0 + mbase + mt * 16 + (lane >> 2);
        int m2 = m1 + 8;
#pragma unroll
        for (int nt = 0; nt < 4; nt++) {
            int nc = nbase + nt * 8 + (lane & 3) * 2;
            if (m1 < M)
                *(__half2*)&g_support[(size_t)m1 * DIM + nc] =
                    __floats2half2_rn(acc[mt][nt][0], acc[mt][nt][1]);
            if (m2 < M)
                *(__half2*)&g_support[(size_t)m2 * DIM + nc] =
                    __floats2half2_rn(acc[mt][nt][2], acc[mt][nt][3]);
        }
    }
}

// ---------------- 2. histogram of edge rows (4 edges/thread) --------------
__global__ void hist_kernel(const int* __restrict__ rows, int e) {
    int i4 = (blockIdx.x * blockDim.x + threadIdx.x) * 4;
    if (i4 + 3 < e) {
        int4 r = *(const int4*)(rows + i4);
        atomicAdd(&g_count[r.x], 1);
        atomicAdd(&g_count[r.y], 1);
        atomicAdd(&g_count[r.z], 1);
        atomicAdd(&g_count[r.w], 1);
    } else {
        for (int i = i4; i < e; i++) atomicAdd(&g_count[rows[i]], 1);
    }
}

// ---------------- 3a. per-block local exclusive scan ----------------------
__global__ __launch_bounds__(SCAN_B) void scan1_kernel(int n) {
    __shared__ int sh[SCAN_B];
    const int tid = threadIdx.x;
    const int idx = blockIdx.x * SCAN_B + tid;

    int v = (idx < n) ? g_count[idx] : 0;
    sh[tid] = v;
    __syncthreads();

#pragma unroll
    for (int off = 1; off < SCAN_B; off <<= 1) {
        int t = (tid >= off) ? sh[tid - off] : 0;
        __syncthreads();
        sh[tid] += t;
        __syncthreads();
    }

    if (idx < n) g_rowptr[idx] = sh[tid] - v;
    if (tid == SCAN_B - 1) g_bsum[blockIdx.x] = sh[SCAN_B - 1];
}

// ---------------- 3b. scan of block sums (1 CTA) ---------------------------
__global__ __launch_bounds__(128) void scan2_kernel(int nblk, int n) {
    __shared__ int sh[128];
    const int tid = threadIdx.x;
    int v = (tid < nblk) ? g_bsum[tid] : 0;
    sh[tid] = v;
    __syncthreads();

#pragma unroll
    for (int off = 1; off < 128; off <<= 1) {
        int t = (tid >= off) ? sh[tid - off] : 0;
        __syncthreads();
        sh[tid] += t;
        __syncthreads();
    }

    if (tid < nblk) g_bsum[tid] = sh[tid] - v;
    if (tid == 127) g_rowptr[n] = sh[127];
}

// ---------------- 3c. add block offsets, materialize head -----------------
__global__ __launch_bounds__(SCAN_B) void scan3_kernel(int n) {
    const int idx = blockIdx.x * SCAN_B + threadIdx.x;
    if (idx < n) {
        int r = g_rowptr[idx] + g_bsum[blockIdx.x];
        g_rowptr[idx] = r;
        g_head[idx]   = r;
    }
}

// ---------------- 4. scatter edges into CSR order (packed int2) -----------
__global__ void scatter_kernel(const int* __restrict__ rows,
                               const int* __restrict__ cols,
                               const float* __restrict__ vals, int e) {
    int i = blockIdx.x * blockDim.x + threadIdx.x;
    if (i < e) {
        int pos = atomicAdd(&g_head[rows[i]], 1);
        g_edge[pos] = make_int2(cols[i], __float_as_int(vals[i]));
    }
}

// ---------------- 5. fused gather + blend + L2-normalize + bias ----------
__global__ __launch_bounds__(256) void agg_kernel(
    const float* __restrict__ input,
    const float* __restrict__ bias,
    float* __restrict__ out, int n)
{
    const int gtid = blockIdx.x * blockDim.x + threadIdx.x;
    const int row  = gtid >> 5;
    const int lane = gtid & 31;
    if (row >= n) return;

    const int start = g_rowptr[row];
    const int end   = g_rowptr[row + 1];

    const uint2* sup8 = (const uint2*)g_support;   // 4 halves per uint2
    float4 acc = make_float4(0.f, 0.f, 0.f, 0.f);

    for (int e0 = start; e0 < end; e0 += 32) {
        int  e = e0 + lane;
        int2 ed = (e < end) ? g_edge[e] : make_int2(0, 0);
        int cnt = min(32, end - e0);
        for (int j = 0; j < cnt; j++) {
            int   cj = __shfl_sync(0xffffffffu, ed.x, j);
            float vj = __int_as_float(__shfl_sync(0xffffffffu, ed.y, j));
            uint2 u  = sup8[cj * DIM4 + lane];
            float2 s0 = __half22float2(*(__half2*)&u.x);
            float2 s1 = __half22float2(*(__half2*)&u.y);
            acc.x = fmaf(vj, s0.x, acc.x);
            acc.y = fmaf(vj, s0.y, acc.y);
            acc.z = fmaf(vj, s1.x, acc.z);
            acc.w = fmaf(vj, s1.y, acc.w);
        }
    }

    float4 in4 = ((const float4*)input)[row * DIM4 + lane];
    float4 o;
    o.x = fmaf(BETA, in4.x, ONE_MB * acc.x);
    o.y = fmaf(BETA, in4.y, ONE_MB * acc.y);
    o.z = fmaf(BETA, in4.z, ONE_MB * acc.z);
    o.w = fmaf(BETA, in4.w, ONE_MB * acc.w);

    float ss = o.x * o.x + o.y * o.y + o.z * o.z + o.w * o.w;
#pragma unroll
    for (int off = 16; off; off >>= 1)
        ss += __shfl_xor_sync(0xffffffffu, ss, off);

    float inv = 1.f / fmaxf(sqrtf(ss), EPS_NORM);

    float4 b4 = ((const float4*)bias)[lane];
    o.x = fmaf(o.x, inv, b4.x);
    o.y = fmaf(o.y, inv, b4.y);
    o.z = fmaf(o.z, inv, b4.z);
    o.w = fmaf(o.w, inv, b4.w);

    ((float4*)out)[row * DIM4 + lane] = o;
}

// ---------------- launch ---------------------------------------------------
// Two-branch graph: CSR build on the main (capture) stream, GEMM chain on a
// side stream, fork/join via events. Streams/events created once (host-side
// resources only; identical GPU work every call).
extern "C" void kernel_launch(void* const* d_in, const int* in_sizes, int n_in,
                              void* d_out, int out_size) {
    const float* input     = (const float*)d_in[0];
    const int*   edge_rows = (const int*)  d_in[1];
    const int*   edge_cols = (const int*)  d_in[2];
    const float* edge_vals = (const float*)d_in[3];
    const float* weight    = (const float*)d_in[4];
    const float* bias      = (const float*)d_in[5];
    float*       out       = (float*)d_out;

    const int n = in_sizes[0] / DIM;   // 100000
    const int e = in_sizes[1];         // 1600000
    const int nblk = NBLK(n);          // 98

    static cudaStream_t s2 = nullptr;
    static cudaEvent_t  ev_fork = nullptr, ev_join = nullptr;
    if (!s2) {
        cudaStreamCreateWithFlags(&s2, cudaStreamNonBlocking);
        cudaEventCreateWithFlags(&ev_fork, cudaEventDisableTiming);
        cudaEventCreateWithFlags(&ev_join, cudaEventDisableTiming);
    }

    // fork: side stream joins the capture after the fork event
    cudaEventRecord(ev_fork, 0);
    cudaStreamWaitEvent(s2, ev_fork, 0);

    // branch B (side stream): dense projection
    wt_kernel<<<(DIM * DIM + 255) / 256, 256, 0, s2>>>(weight);
    gemm_hmma_kernel<<<(n + 127) / 128, 256, 0, s2>>>(input, n);
    cudaEventRecord(ev_join, s2);

    // branch A (main stream): CSR build
    zero_count_kernel<<<(n + 255) / 256, 256>>>(n);
    hist_kernel<<<(e / 4 + 255) / 256, 256>>>(edge_rows, e);
    scan1_kernel<<<nblk, SCAN_B>>>(n);
    scan2_kernel<<<1, 128>>>(nblk, n);
    scan3_kernel<<<nblk, SCAN_B>>>(n);
    scatter_kernel<<<(e + 255) / 256, 256>>>(edge_rows, edge_cols, edge_vals, e);

    // join: agg needs both support (branch B) and CSR (branch A)
    cudaStreamWaitEvent(0, ev_join, 0);
    agg_kernel<<<((long long)n * 32 + 255) / 256, 256>>>(input, bias, out, n);
}

// round 9
// speedup vs baseline: 3.0416x; 1.0003x over previous
#include <cuda_runtime.h>
#include <cuda_fp16.h>
#include <math.h>
#include <stdint.h>

#define DIM      128
#define DIM4     32          // DIM / 4
#define MAXN     100000
#define MAXE     1600000
#define BETA     0.001f
#define ONE_MB   0.999f      // 1 - BETA
#define EPS_NORM 1e-12f

#define SCAN_B   1024
#define NBLK(n)  (((n) + SCAN_B - 1) / SCAN_B)

#define BK        64                 // K elements per smem pass
#define AS_STRIDE (BK + 8)           // 72 halves = 144B row stride

// ---------------- device scratch (no allocations allowed) ----------------
__device__ __half g_support[(size_t)MAXN * DIM];  // 25.6 MB, L2-resident
__device__ __half g_wt[DIM * DIM];                // W^T, [n][k] fp16
__device__ int    g_count [MAXN];
__device__ int    g_rowptr[MAXN + 1];
__device__ int    g_head  [MAXN];
__device__ int2   g_edge  [MAXE];                 // packed (col, val-bits)
__device__ int    g_bsum  [128];

// ---------------- PTX helpers ---------------------------------------------
__device__ __forceinline__ uint32_t smem_u32(const void* p) {
    return (uint32_t)__cvta_generic_to_shared(p);
}
__device__ __forceinline__ void ldm_x4(uint32_t& r0, uint32_t& r1,
                                       uint32_t& r2, uint32_t& r3, uint32_t addr) {
    asm volatile("ldmatrix.sync.aligned.m8n8.x4.shared.b16 {%0,%1,%2,%3}, [%4];"
        : "=r"(r0), "=r"(r1), "=r"(r2), "=r"(r3) : "r"(addr));
}
__device__ __forceinline__ void mma16816(float* c, const uint32_t* a, const uint32_t* b) {
    asm volatile("mma.sync.aligned.m16n8k16.row.col.f32.f16.f16.f32 "
        "{%0,%1,%2,%3}, {%4,%5,%6,%7}, {%8,%9}, {%0,%1,%2,%3};"
        : "+f"(c[0]), "+f"(c[1]), "+f"(c[2]), "+f"(c[3])
        : "r"(a[0]), "r"(a[1]), "r"(a[2]), "r"(a[3]), "r"(b[0]), "r"(b[1]));
}

// ---------------- 0. zero the per-row edge counters ----------------------
__global__ void zero_count_kernel(int n) {
    int i = blockIdx.x * blockDim.x + threadIdx.x;
    if (i < n) g_count[i] = 0;
}

// ---------------- 0b. W [k][n] fp32 -> g_wt [n][k] fp16 -------------------
__global__ void wt_kernel(const float* __restrict__ W) {
    int tid = blockIdx.x * blockDim.x + threadIdx.x;
    if (tid < DIM * DIM) {
        int n = tid >> 7, k = tid & 127;
        g_wt[n * DIM + k] = __float2half_rn(W[k * DIM + n]);
    }
}

// ---------------- 1. support = input @ W  (HMMA fp16, fp32 accum) --------
__global__ __launch_bounds__(256) void gemm_hmma_kernel(
    const float* __restrict__ A, int M)
{
    __shared__ __half As[128 * AS_STRIDE];   // [m][k_local]
    __shared__ __half Ws[128 * AS_STRIDE];   // [n][k_local]

    const int tid  = threadIdx.x;
    const int warp = tid >> 5;
    const int lane = tid & 31;
    const int m0   = blockIdx.x * 128;

    const int wm = warp & 1;
    const int wn = warp >> 1;
    const int mbase = wm * 64;
    const int nbase = wn * 32;

    float acc[4][4][4];
#pragma unroll
    for (int i = 0; i < 4; i++)
#pragma unroll
        for (int j = 0; j < 4; j++)
#pragma unroll
            for (int q = 0; q < 4; q++) acc[i][j][q] = 0.f;

    const float4* A4 = (const float4*)A;
    const uint32_t as_base = smem_u32(As);
    const uint32_t ws_base = smem_u32(Ws);

    const int mat = lane >> 3;
    const int rin = lane & 7;
    const int rofs = rin + (mat & 1) * 8;
    const int kofs = (mat >> 1) * 8;

    for (int pass = 0; pass < 2; pass++) {
        const int kg = pass * BK;

#pragma unroll
        for (int it = 0; it < 8; it++) {
            int idx4 = tid + it * 256;
            int row  = idx4 >> 4;
            int c4   = idx4 & 15;
            int rg   = m0 + row; if (rg >= M) rg = M - 1;
            float4 f = A4[(size_t)rg * DIM4 + (kg >> 2) + c4];
            __half2* dst = (__half2*)&As[row * AS_STRIDE + c4 * 4];
            dst[0] = __floats2half2_rn(f.x, f.y);
            dst[1] = __floats2half2_rn(f.z, f.w);
        }
#pragma unroll
        for (int it = 0; it < 4; it++) {
            int idx8 = tid + it * 256;
            int row  = idx8 >> 3;
            int c8   = idx8 & 7;
            uint4 u = *(const uint4*)&g_wt[row * DIM + kg + c8 * 8];
            *(uint4*)&Ws[row * AS_STRIDE + c8 * 8] = u;
        }
        __syncthreads();

#pragma unroll
        for (int ks = 0; ks < BK / 16; ks++) {
            const int k0 = ks * 16;

            uint32_t a[4][4];
#pragma unroll
            for (int mt = 0; mt < 4; mt++) {
                uint32_t addr = as_base +
                    ((mbase + mt * 16 + rofs) * AS_STRIDE + k0 + kofs) * 2;
                ldm_x4(a[mt][0], a[mt][1], a[mt][2], a[mt][3], addr);
            }
            uint32_t b[4][2];
#pragma unroll
            for (int g = 0; g < 2; g++) {
                uint32_t addr = ws_base +
                    ((nbase + g * 16 + rofs) * AS_STRIDE + k0 + kofs) * 2;
                uint32_t r0, r1, r2, r3;
                ldm_x4(r0, r1, r2, r3, addr);
                b[g * 2 + 0][0] = r0; b[g * 2 + 0][1] = r2;
                b[g * 2 + 1][0] = r1; b[g * 2 + 1][1] = r3;
            }
#pragma unroll
            for (int mt = 0; mt < 4; mt++)
#pragma unroll
                for (int nt = 0; nt < 4; nt++)
                    mma16816(acc[mt][nt], a[mt], b[nt]);
        }
        __syncthreads();
    }

#pragma unroll
    for (int mt = 0; mt < 4; mt++) {
        int m1 = m0 + mbase + mt * 16 + (lane >> 2);
        int m2 = m1 + 8;
#pragma unroll
        for (int nt = 0; nt < 4; nt++) {
            int nc = nbase + nt * 8 + (lane & 3) * 2;
            if (m1 < M)
                *(__half2*)&g_support[(size_t)m1 * DIM + nc] =
                    __floats2half2_rn(acc[mt][nt][0], acc[mt][nt][1]);
            if (m2 < M)
                *(__half2*)&g_support[(size_t)m2 * DIM + nc] =
                    __floats2half2_rn(acc[mt][nt][2], acc[mt][nt][3]);
        }
    }
}

// ---------------- 2. histogram of edge rows (4 edges/thread) --------------
__global__ void hist_kernel(const int* __restrict__ rows, int e) {
    int i4 = (blockIdx.x * blockDim.x + threadIdx.x) * 4;
    if (i4 + 3 < e) {
        int4 r = *(const int4*)(rows + i4);
        atomicAdd(&g_count[r.x], 1);
        atomicAdd(&g_count[r.y], 1);
        atomicAdd(&g_count[r.z], 1);
        atomicAdd(&g_count[r.w], 1);
    } else {
        for (int i = i4; i < e; i++) atomicAdd(&g_count[rows[i]], 1);
    }
}

// ---------------- 3a. per-block local exclusive scan ----------------------
__global__ __launch_bounds__(SCAN_B) void scan1_kernel(int n) {
    __shared__ int sh[SCAN_B];
    const int tid = threadIdx.x;
    const int idx = blockIdx.x * SCAN_B + tid;

    int v = (idx < n) ? g_count[idx] : 0;
    sh[tid] = v;
    __syncthreads();

#pragma unroll
    for (int off = 1; off < SCAN_B; off <<= 1) {
        int t = (tid >= off) ? sh[tid - off] : 0;
        __syncthreads();
        sh[tid] += t;
        __syncthreads();
    }

    if (idx < n) g_rowptr[idx] = sh[tid] - v;
    if (tid == SCAN_B - 1) g_bsum[blockIdx.x] = sh[SCAN_B - 1];
}

// ---------------- 3b. scan of block sums (1 CTA) ---------------------------
__global__ __launch_bounds__(128) void scan2_kernel(int nblk, int n) {
    __shared__ int sh[128];
    const int tid = threadIdx.x;
    int v = (tid < nblk) ? g_bsum[tid] : 0;
    sh[tid] = v;
    __syncthreads();

#pragma unroll
    for (int off = 1; off < 128; off <<= 1) {
        int t = (tid >= off) ? sh[tid - off] : 0;
        __syncthreads();
        sh[tid] += t;
        __syncthreads();
    }

    if (tid < nblk) g_bsum[tid] = sh[tid] - v;
    if (tid == 127) g_rowptr[n] = sh[127];
}

// ---------------- 3c. add block offsets, materialize head -----------------
__global__ __launch_bounds__(SCAN_B) void scan3_kernel(int n) {
    const int idx = blockIdx.x * SCAN_B + threadIdx.x;
    if (idx < n) {
        int r = g_rowptr[idx] + g_bsum[blockIdx.x];
        g_rowptr[idx] = r;
        g_head[idx]   = r;
    }
}

// ---------------- 4. scatter edges into CSR order (packed int2) -----------
__global__ void scatter_kernel(const int* __restrict__ rows,
                               const int* __restrict__ cols,
                               const float* __restrict__ vals, int e) {
    int i = blockIdx.x * blockDim.x + threadIdx.x;
    if (i < e) {
        int pos = atomicAdd(&g_head[rows[i]], 1);
        g_edge[pos] = make_int2(cols[i], __float_as_int(vals[i]));
    }
}

// ---------------- 5. fused gather + blend + L2-normalize + bias ----------
__global__ __launch_bounds__(256) void agg_kernel(
    const float* __restrict__ input,
    const float* __restrict__ bias,
    float* __restrict__ out, int n)
{
    const int gtid = blockIdx.x * blockDim.x + threadIdx.x;
    const int row  = gtid >> 5;
    const int lane = gtid & 31;
    if (row >= n) return;

    const int start = g_rowptr[row];
    const int end   = g_rowptr[row + 1];

    const uint2* sup8 = (const uint2*)g_support;   // 4 halves per uint2
    float4 acc = make_float4(0.f, 0.f, 0.f, 0.f);

    for (int e0 = start; e0 < end; e0 += 32) {
        int  e = e0 + lane;
        int2 ed = (e < end) ? g_edge[e] : make_int2(0, 0);
        int cnt = min(32, end - e0);
        for (int j = 0; j < cnt; j++) {
            int   cj = __shfl_sync(0xffffffffu, ed.x, j);
            float vj = __int_as_float(__shfl_sync(0xffffffffu, ed.y, j));
            uint2 u  = sup8[cj * DIM4 + lane];
            float2 s0 = __half22float2(*(__half2*)&u.x);
            float2 s1 = __half22float2(*(__half2*)&u.y);
            acc.x = fmaf(vj, s0.x, acc.x);
            acc.y = fmaf(vj, s0.y, acc.y);
            acc.z = fmaf(vj, s1.x, acc.z);
            acc.w = fmaf(vj, s1.y, acc.w);
        }
    }

    float4 in4 = ((const float4*)input)[row * DIM4 + lane];
    float4 o;
    o.x = fmaf(BETA, in4.x, ONE_MB * acc.x);
    o.y = fmaf(BETA, in4.y, ONE_MB * acc.y);
    o.z = fmaf(BETA, in4.z, ONE_MB * acc.z);
    o.w = fmaf(BETA, in4.w, ONE_MB * acc.w);

    float ss = o.x * o.x + o.y * o.y + o.z * o.z + o.w * o.w;
#pragma unroll
    for (int off = 16; off; off >>= 1)
        ss += __shfl_xor_sync(0xffffffffu, ss, off);

    float inv = 1.f / fmaxf(sqrtf(ss), EPS_NORM);

    float4 b4 = ((const float4*)bias)[lane];
    o.x = fmaf(o.x, inv, b4.x);
    o.y = fmaf(o.y, inv, b4.y);
    o.z = fmaf(o.z, inv, b4.z);
    o.w = fmaf(o.w, inv, b4.w);

    ((float4*)out)[row * DIM4 + lane] = o;
}

// ---------------- launch ---------------------------------------------------
// Two-branch graph: CSR build on the main (capture) stream, GEMM chain on a
// side stream, fork/join via events. Streams/events created once (host-side
// resources only; identical GPU work every call).
extern "C" void kernel_launch(void* const* d_in, const int* in_sizes, int n_in,
                              void* d_out, int out_size) {
    const float* input     = (const float*)d_in[0];
    const int*   edge_rows = (const int*)  d_in[1];
    const int*   edge_cols = (const int*)  d_in[2];
    const float* edge_vals = (const float*)d_in[3];
    const float* weight    = (const float*)d_in[4];
    const float* bias      = (const float*)d_in[5];
    float*       out       = (float*)d_out;

    const int n = in_sizes[0] / DIM;   // 100000
    const int e = in_sizes[1];         // 1600000
    const int nblk = NBLK(n);          // 98

    static cudaStream_t s2 = nullptr;
    static cudaEvent_t  ev_fork = nullptr, ev_join = nullptr;
    if (!s2) {
        cudaStreamCreateWithFlags(&s2, cudaStreamNonBlocking);
        cudaEventCreateWithFlags(&ev_fork, cudaEventDisableTiming);
        cudaEventCreateWithFlags(&ev_join, cudaEventDisableTiming);
    }

    // fork: side stream joins the capture after the fork event
    cudaEventRecord(ev_fork, 0);
    cudaStreamWaitEvent(s2, ev_fork, 0);

    // branch B (side stream): dense projection
    wt_kernel<<<(DIM * DIM + 255) / 256, 256, 0, s2>>>(weight);
    gemm_hmma_kernel<<<(n + 127) / 128, 256, 0, s2>>>(input, n);
    cudaEventRecord(ev_join, s2);

    // branch A (main stream): CSR build
    zero_count_kernel<<<(n + 255) / 256, 256>>>(n);
    hist_kernel<<<(e / 4 + 255) / 256, 256>>>(edge_rows, e);
    scan1_kernel<<<nblk, SCAN_B>>>(n);
    scan2_kernel<<<1, 128>>>(nblk, n);
    scan3_kernel<<<nblk, SCAN_B>>>(n);
    scatter_kernel<<<(e + 255) / 256, 256>>>(edge_rows, edge_cols, edge_vals, e);

    // join: agg needs both support (branch B) and CSR (branch A)
    cudaStreamWaitEvent(0, ev_join, 0);
    agg_kernel<<<((long long)n * 32 + 255) / 256, 256>>>(input, bias, out, n);
}